// round 2
// baseline (speedup 1.0000x reference)
#include <cuda_runtime.h>
#include <cstdint>
#include <cmath>

// Problem constants
#define BATCH   4
#define SEQ     1024
#define DM      1024      // d_model
#define NHEAD   16
#define DK      64
#define MROWS   (BATCH*SEQ)   // 4096
#define LN_EPS  1e-5f

// ---------------- scratch (device globals; no allocs allowed) ----------------
__device__ float g_Qp[MROWS * DM];
__device__ float g_Kp[MROWS * DM];
__device__ float g_Vp[MROWS * DM];
__device__ float g_heads[MROWS * DM];
__device__ float g_tmp[MROWS * DM];

// ---------------- SGEMM: C[m,n] = sum_k A[m,k]*W[n,k] + bias[n] (+resid) -----
// A: [M,K] row-major, W: [N,K] row-major (i.e. computes A @ W^T)
// BM=BN=128, BK=8, 256 threads, 8x8 per thread.
__global__ __launch_bounds__(256) void sgemm_bias(
    const float* __restrict__ A, const float* __restrict__ W,
    const float* __restrict__ bias, const float* __restrict__ resid,
    float* __restrict__ C, int M, int N, int K)
{
    __shared__ float As[8][128];
    __shared__ float Ws[8][128];

    const int tid = threadIdx.x;
    const int bm = blockIdx.y * 128;
    const int bn = blockIdx.x * 128;

    const int aRow = tid >> 1;            // 0..127
    const int aCol = (tid & 1) * 4;       // 0 or 4
    const float* Aptr = A + (size_t)(bm + aRow) * K + aCol;
    const float* Wptr = W + (size_t)(bn + aRow) * K + aCol;

    const int ty = tid >> 4;              // 0..15  (row group)
    const int tx = tid & 15;              // 0..15  (col group)

    float acc[8][8];
    #pragma unroll
    for (int i = 0; i < 8; i++)
        #pragma unroll
        for (int j = 0; j < 8; j++) acc[i][j] = 0.f;

    for (int k0 = 0; k0 < K; k0 += 8) {
        float4 a4 = *reinterpret_cast<const float4*>(Aptr + k0);
        float4 w4 = *reinterpret_cast<const float4*>(Wptr + k0);
        __syncthreads();
        As[aCol + 0][aRow] = a4.x; As[aCol + 1][aRow] = a4.y;
        As[aCol + 2][aRow] = a4.z; As[aCol + 3][aRow] = a4.w;
        Ws[aCol + 0][aRow] = w4.x; Ws[aCol + 1][aRow] = w4.y;
        Ws[aCol + 2][aRow] = w4.z; Ws[aCol + 3][aRow] = w4.w;
        __syncthreads();

        #pragma unroll
        for (int kk = 0; kk < 8; kk++) {
            const float4* ap = reinterpret_cast<const float4*>(&As[kk][ty * 8]);
            const float4* wp = reinterpret_cast<const float4*>(&Ws[kk][tx * 8]);
            float4 a0 = ap[0], a1 = ap[1];
            float4 w0 = wp[0], w1 = wp[1];
            float ra[8] = {a0.x, a0.y, a0.z, a0.w, a1.x, a1.y, a1.z, a1.w};
            float rw[8] = {w0.x, w0.y, w0.z, w0.w, w1.x, w1.y, w1.z, w1.w};
            #pragma unroll
            for (int i = 0; i < 8; i++)
                #pragma unroll
                for (int j = 0; j < 8; j++)
                    acc[i][j] = fmaf(ra[i], rw[j], acc[i][j]);
        }
    }

    #pragma unroll
    for (int i = 0; i < 8; i++) {
        int m = bm + ty * 8 + i;
        #pragma unroll
        for (int j = 0; j < 8; j++) {
            int n = bn + tx * 8 + j;
            float v = acc[i][j] + bias[n];
            if (resid) v += resid[(size_t)m * N + n];
            C[(size_t)m * N + n] = v;
        }
    }
}

// ---------------- Attention kernel --------------------------------------------
// One block = (b, h, 32 query rows). Score tile in smem, fused gate/mask/softmax,
// writes attn probs to global and does PV from smem.
#define LKV 65   // padded leading dim for K/V chunk (conflict-free)

__global__ __launch_bounds__(256) void attn_kernel(
    const float* __restrict__ Qp, const float* __restrict__ Kp,
    const float* __restrict__ Vp, const float* __restrict__ gate,
    const int* __restrict__ mask,
    float* __restrict__ attn, float* __restrict__ heads)
{
    extern __shared__ float sm[];
    float* S  = sm;                    // [32][1024]
    float* Qs = S + 32 * 1024;         // [32][64]
    float* KV = Qs + 32 * 64;          // [128][LKV]

    const int b = blockIdx.z, h = blockIdx.y;
    const int q0 = blockIdx.x * 32;
    const int tid = threadIdx.x;
    const int ty = tid >> 5;           // warp id 0..7
    const int tx = tid & 31;           // lane

    // load Q tile [32][64]
    for (int i = tid; i < 32 * 64; i += 256) {
        int r = i >> 6, d = i & 63;
        Qs[r * 64 + d] = Qp[((size_t)(b * SEQ + q0 + r)) * DM + h * DK + d];
    }

    const float inv_temp = 0.125f;   // 1/sqrt(64)

    // ---- QK^T, gate, mask ----
    for (int kc = 0; kc < 8; kc++) {
        __syncthreads();
        for (int i = tid; i < 128 * 64; i += 256) {
            int r = i >> 6, d = i & 63;
            KV[r * LKV + d] = Kp[((size_t)(b * SEQ + kc * 128 + r)) * DM + h * DK + d];
        }
        __syncthreads();

        float acc[4][4];
        #pragma unroll
        for (int ii = 0; ii < 4; ii++)
            #pragma unroll
            for (int jj = 0; jj < 4; jj++) acc[ii][jj] = 0.f;

        #pragma unroll 8
        for (int d = 0; d < 64; d++) {
            float qv[4], kv[4];
            #pragma unroll
            for (int ii = 0; ii < 4; ii++) qv[ii] = Qs[(ty * 4 + ii) * 64 + d];
            #pragma unroll
            for (int jj = 0; jj < 4; jj++) kv[jj] = KV[(tx + jj * 32) * LKV + d];
            #pragma unroll
            for (int ii = 0; ii < 4; ii++)
                #pragma unroll
                for (int jj = 0; jj < 4; jj++)
                    acc[ii][jj] = fmaf(qv[ii], kv[jj], acc[ii][jj]);
        }

        #pragma unroll
        for (int ii = 0; ii < 4; ii++) {
            int q = q0 + ty * 4 + ii;
            const float* grow = gate + (((size_t)(b * NHEAD + h) * SEQ + q)) * SEQ + kc * 128;
            const int* mrow = mask + ((size_t)(b * SEQ + q)) * SEQ + kc * 128;
            #pragma unroll
            for (int jj = 0; jj < 4; jj++) {
                int j = tx + jj * 32;
                float s = acc[ii][jj] * inv_temp * grow[j];
                if (mrow[j] != 0) s = -INFINITY;
                S[(ty * 4 + ii) * 1024 + kc * 128 + j] = s;
            }
        }
    }
    __syncthreads();

    // ---- softmax (warp per row group) + write attn ----
    for (int ii = 0; ii < 4; ii++) {
        int r = ty * 4 + ii;
        float* srow = S + r * 1024;
        float mx = -INFINITY;
        for (int j = tx; j < 1024; j += 32) mx = fmaxf(mx, srow[j]);
        #pragma unroll
        for (int o = 16; o; o >>= 1) mx = fmaxf(mx, __shfl_xor_sync(0xffffffffu, mx, o));
        float sum = 0.f;
        for (int j = tx; j < 1024; j += 32) {
            float e = __expf(srow[j] - mx);
            srow[j] = e;
            sum += e;
        }
        #pragma unroll
        for (int o = 16; o; o >>= 1) sum += __shfl_xor_sync(0xffffffffu, sum, o);
        float inv = 1.f / sum;
        float* arow = attn + (((size_t)(b * NHEAD + h) * SEQ) + q0 + r) * SEQ;
        for (int j = tx; j < 1024; j += 32) {
            float p = srow[j] * inv;
            srow[j] = p;
            arow[j] = p;
        }
    }

    // ---- PV: out[32][64] = S[32][1024] @ V[1024][64] ----
    float oacc[4][2];
    #pragma unroll
    for (int ii = 0; ii < 4; ii++) { oacc[ii][0] = 0.f; oacc[ii][1] = 0.f; }

    for (int kc = 0; kc < 8; kc++) {
        __syncthreads();
        for (int i = tid; i < 128 * 64; i += 256) {
            int r = i >> 6, d = i & 63;
            KV[r * LKV + d] = Vp[((size_t)(b * SEQ + kc * 128 + r)) * DM + h * DK + d];
        }
        __syncthreads();

        #pragma unroll 4
        for (int j = 0; j < 128; j++) {
            float v0 = KV[j * LKV + tx];
            float v1 = KV[j * LKV + tx + 32];
            #pragma unroll
            for (int ii = 0; ii < 4; ii++) {
                float p = S[(ty * 4 + ii) * 1024 + kc * 128 + j];
                oacc[ii][0] = fmaf(p, v0, oacc[ii][0]);
                oacc[ii][1] = fmaf(p, v1, oacc[ii][1]);
            }
        }
    }

    #pragma unroll
    for (int ii = 0; ii < 4; ii++) {
        int q = q0 + ty * 4 + ii;
        float* orow = heads + ((size_t)(b * SEQ + q)) * DM + h * DK;
        orow[tx]      = oacc[ii][0];
        orow[tx + 32] = oacc[ii][1];
    }
}

// ---------------- LayerNorm: one block per row (1024 elems) -------------------
__global__ __launch_bounds__(256) void ln_kernel(
    const float* __restrict__ X, const float* __restrict__ gamma,
    const float* __restrict__ beta, float* __restrict__ out)
{
    __shared__ float sh1[8];
    __shared__ float sh2[8];
    const int row = blockIdx.x;
    const int tid = threadIdx.x;
    const float* x = X + (size_t)row * DM;

    float v[4];
    float s = 0.f;
    #pragma unroll
    for (int i = 0; i < 4; i++) { v[i] = x[tid + i * 256]; s += v[i]; }
    #pragma unroll
    for (int o = 16; o; o >>= 1) s += __shfl_xor_sync(0xffffffffu, s, o);
    if ((tid & 31) == 0) sh1[tid >> 5] = s;
    __syncthreads();
    float tot = 0.f;
    #pragma unroll
    for (int w = 0; w < 8; w++) tot += sh1[w];
    float mu = tot * (1.f / DM);

    float vs = 0.f;
    #pragma unroll
    for (int i = 0; i < 4; i++) { float d = v[i] - mu; vs += d * d; }
    #pragma unroll
    for (int o = 16; o; o >>= 1) vs += __shfl_xor_sync(0xffffffffu, vs, o);
    if ((tid & 31) == 0) sh2[tid >> 5] = vs;
    __syncthreads();
    float tv = 0.f;
    #pragma unroll
    for (int w = 0; w < 8; w++) tv += sh2[w];
    float var = tv * (1.f / DM);
    float inv = rsqrtf(var + LN_EPS);

    float* orow = out + (size_t)row * DM;
    #pragma unroll
    for (int i = 0; i < 4; i++) {
        int c = tid + i * 256;
        orow[c] = (v[i] - mu) * inv * gamma[c] + beta[c];
    }
}

// ---------------- launch -------------------------------------------------------
extern "C" void kernel_launch(void* const* d_in, const int* in_sizes, int n_in,
                              void* d_out, int out_size)
{
    const float* q       = (const float*)d_in[0];
    const float* k       = (const float*)d_in[1];
    const float* v       = (const float*)d_in[2];
    const float* k_gate  = (const float*)d_in[3];
    const int*   mask    = (const int*)d_in[4];
    const float* Wq = (const float*)d_in[5];
    const float* bq = (const float*)d_in[6];
    const float* Wk = (const float*)d_in[7];
    const float* bk = (const float*)d_in[8];
    const float* Wv = (const float*)d_in[9];
    const float* bv = (const float*)d_in[10];
    const float* Wo = (const float*)d_in[11];
    const float* bo = (const float*)d_in[12];
    const float* ln_g = (const float*)d_in[13];
    const float* ln_b = (const float*)d_in[14];

    float* out  = (float*)d_out;                                  // [4,1024,1024]
    float* attn = out + (size_t)BATCH * SEQ * DM;                 // [4,16,1024,1024]

    float *Qp, *Kp, *Vp, *heads, *tmp;
    cudaGetSymbolAddress((void**)&Qp, g_Qp);
    cudaGetSymbolAddress((void**)&Kp, g_Kp);
    cudaGetSymbolAddress((void**)&Vp, g_Vp);
    cudaGetSymbolAddress((void**)&heads, g_heads);
    cudaGetSymbolAddress((void**)&tmp, g_tmp);

    const int ATTN_SMEM = (32 * 1024 + 32 * 64 + 128 * LKV) * (int)sizeof(float);
    cudaFuncSetAttribute(attn_kernel, cudaFuncAttributeMaxDynamicSharedMemorySize, ATTN_SMEM);

    dim3 gblk(256);
    dim3 ggrid(DM / 128, MROWS / 128);   // (8, 32)

    // Q/K/V projections
    sgemm_bias<<<ggrid, gblk>>>(q, Wq, bq, nullptr, Qp, MROWS, DM, DM);
    sgemm_bias<<<ggrid, gblk>>>(k, Wk, bk, nullptr, Kp, MROWS, DM, DM);
    sgemm_bias<<<ggrid, gblk>>>(v, Wv, bv, nullptr, Vp, MROWS, DM, DM);

    // Attention + attn output + heads
    dim3 agrid(SEQ / 32, NHEAD, BATCH);  // (32,16,4)
    attn_kernel<<<agrid, 256, ATTN_SMEM>>>(Qp, Kp, Vp, k_gate, mask, attn, heads);

    // Output projection + residual
    sgemm_bias<<<ggrid, gblk>>>(heads, Wo, bo, q, tmp, MROWS, DM, DM);

    // LayerNorm -> final out
    ln_kernel<<<MROWS, 256>>>(tmp, ln_g, ln_b, out);
}

// round 3
// speedup vs baseline: 1.4808x; 1.4808x over previous
#include <cuda_runtime.h>
#include <cstdint>
#include <cmath>

// Problem constants
#define BATCH   4
#define SEQ     1024
#define DM      1024
#define NHEAD   16
#define DK      64
#define MROWS   (BATCH*SEQ)   // 4096
#define LN_EPS  1e-5f

// ---------------- scratch (device globals) ----------------
__device__ float g_Qp[MROWS * DM];
__device__ float g_Kp[MROWS * DM];
__device__ float g_Vp[MROWS * DM];
__device__ float g_heads[MROWS * DM];
__device__ float g_tmp[MROWS * DM];

// =====================================================================
// TF32x3 tensor-core GEMM:  C[m,n] = sum_k A[m,k]*W[n,k] + bias[n] (+resid)
// BM=128, BN=128, BK=16, 256 threads (8 warps), warp tile 64x32.
// A/B split into tf32 hi/lo at smem-store time; 3 MMAs per tile (hh, hl, lh).
// =====================================================================

__device__ __forceinline__ uint32_t f32_to_tf32(float x) {
    uint32_t r;
    asm("cvt.rna.tf32.f32 %0, %1;" : "=r"(r) : "f"(x));
    return r;
}

#define LDA 132
#define LDB 136

__global__ __launch_bounds__(256) void tf32_gemm(
    const float* __restrict__ A, const float* __restrict__ W,
    const float* __restrict__ bias, const float* __restrict__ resid,
    float* __restrict__ C, int M, int N, int K)
{
    __shared__ float AsH[16 * LDA];
    __shared__ float AsL[16 * LDA];
    __shared__ float BsH[16 * LDB];
    __shared__ float BsL[16 * LDB];

    const int tid = threadIdx.x;
    const int bm = blockIdx.y * 128;
    const int bn = blockIdx.x * 128;

    const int wid  = tid >> 5;
    const int lane = tid & 31;
    const int g = lane >> 2;        // group id 0..7
    const int t = lane & 3;         // thread-in-group 0..3
    const int warpM = (wid >> 2) * 64;   // 0 or 64
    const int warpN = (wid & 3) * 32;    // 0,32,64,96

    float c[4][4][4];
    #pragma unroll
    for (int mt = 0; mt < 4; mt++)
        #pragma unroll
        for (int nt = 0; nt < 4; nt++)
            #pragma unroll
            for (int i = 0; i < 4; i++) c[mt][nt][i] = 0.f;

    for (int k0 = 0; k0 < K; k0 += 16) {
        __syncthreads();
        #pragma unroll
        for (int it = 0; it < 2; it++) {
            int idx = it * 256 + tid;
            int row = idx >> 2;
            int cc  = (idx & 3) * 4;
            float4 a = *reinterpret_cast<const float4*>(A + (size_t)(bm + row) * K + k0 + cc);
            float4 w = *reinterpret_cast<const float4*>(W + (size_t)(bn + row) * K + k0 + cc);
            float av[4] = {a.x, a.y, a.z, a.w};
            float wv[4] = {w.x, w.y, w.z, w.w};
            #pragma unroll
            for (int j = 0; j < 4; j++) {
                uint32_t h = f32_to_tf32(av[j]);
                float hf = __uint_as_float(h);
                uint32_t l = f32_to_tf32(av[j] - hf);
                AsH[(cc + j) * LDA + row] = hf;
                AsL[(cc + j) * LDA + row] = __uint_as_float(l);
                uint32_t hw = f32_to_tf32(wv[j]);
                float hwf = __uint_as_float(hw);
                uint32_t lw = f32_to_tf32(wv[j] - hwf);
                BsH[(cc + j) * LDB + row] = hwf;
                BsL[(cc + j) * LDB + row] = __uint_as_float(lw);
            }
        }
        __syncthreads();

        #pragma unroll
        for (int kk = 0; kk < 16; kk += 8) {
            uint32_t aH[4][4], aL[4][4], bH[4][2], bL[4][2];
            #pragma unroll
            for (int mt = 0; mt < 4; mt++) {
                int r0 = warpM + mt * 16 + g;
                int r1 = r0 + 8;
                aH[mt][0] = __float_as_uint(AsH[(kk + t) * LDA + r0]);
                aH[mt][1] = __float_as_uint(AsH[(kk + t) * LDA + r1]);
                aH[mt][2] = __float_as_uint(AsH[(kk + t + 4) * LDA + r0]);
                aH[mt][3] = __float_as_uint(AsH[(kk + t + 4) * LDA + r1]);
                aL[mt][0] = __float_as_uint(AsL[(kk + t) * LDA + r0]);
                aL[mt][1] = __float_as_uint(AsL[(kk + t) * LDA + r1]);
                aL[mt][2] = __float_as_uint(AsL[(kk + t + 4) * LDA + r0]);
                aL[mt][3] = __float_as_uint(AsL[(kk + t + 4) * LDA + r1]);
            }
            #pragma unroll
            for (int nt = 0; nt < 4; nt++) {
                int cn = warpN + nt * 8 + g;
                bH[nt][0] = __float_as_uint(BsH[(kk + t) * LDB + cn]);
                bH[nt][1] = __float_as_uint(BsH[(kk + t + 4) * LDB + cn]);
                bL[nt][0] = __float_as_uint(BsL[(kk + t) * LDB + cn]);
                bL[nt][1] = __float_as_uint(BsL[(kk + t + 4) * LDB + cn]);
            }
            #pragma unroll
            for (int mt = 0; mt < 4; mt++)
                #pragma unroll
                for (int nt = 0; nt < 4; nt++) {
                    float* cc = c[mt][nt];
                    asm volatile(
                        "mma.sync.aligned.m16n8k8.row.col.f32.tf32.tf32.f32 "
                        "{%0,%1,%2,%3}, {%4,%5,%6,%7}, {%8,%9}, {%0,%1,%2,%3};"
                        : "+f"(cc[0]), "+f"(cc[1]), "+f"(cc[2]), "+f"(cc[3])
                        : "r"(aH[mt][0]), "r"(aH[mt][1]), "r"(aH[mt][2]), "r"(aH[mt][3]),
                          "r"(bH[nt][0]), "r"(bH[nt][1]));
                    asm volatile(
                        "mma.sync.aligned.m16n8k8.row.col.f32.tf32.tf32.f32 "
                        "{%0,%1,%2,%3}, {%4,%5,%6,%7}, {%8,%9}, {%0,%1,%2,%3};"
                        : "+f"(cc[0]), "+f"(cc[1]), "+f"(cc[2]), "+f"(cc[3])
                        : "r"(aH[mt][0]), "r"(aH[mt][1]), "r"(aH[mt][2]), "r"(aH[mt][3]),
                          "r"(bL[nt][0]), "r"(bL[nt][1]));
                    asm volatile(
                        "mma.sync.aligned.m16n8k8.row.col.f32.tf32.tf32.f32 "
                        "{%0,%1,%2,%3}, {%4,%5,%6,%7}, {%8,%9}, {%0,%1,%2,%3};"
                        : "+f"(cc[0]), "+f"(cc[1]), "+f"(cc[2]), "+f"(cc[3])
                        : "r"(aL[mt][0]), "r"(aL[mt][1]), "r"(aL[mt][2]), "r"(aL[mt][3]),
                          "r"(bH[nt][0]), "r"(bH[nt][1]));
                }
        }
    }

    // epilogue
    #pragma unroll
    for (int mt = 0; mt < 4; mt++) {
        int r0 = bm + warpM + mt * 16 + g;
        int r1 = r0 + 8;
        #pragma unroll
        for (int nt = 0; nt < 4; nt++) {
            int cn = bn + warpN + nt * 8 + 2 * t;
            float b0 = bias[cn], b1 = bias[cn + 1];
            float v00 = c[mt][nt][0] + b0, v01 = c[mt][nt][1] + b1;
            float v10 = c[mt][nt][2] + b0, v11 = c[mt][nt][3] + b1;
            if (resid) {
                const float2 rA = *reinterpret_cast<const float2*>(resid + (size_t)r0 * N + cn);
                const float2 rB = *reinterpret_cast<const float2*>(resid + (size_t)r1 * N + cn);
                v00 += rA.x; v01 += rA.y; v10 += rB.x; v11 += rB.y;
            }
            *reinterpret_cast<float2*>(C + (size_t)r0 * N + cn) = make_float2(v00, v01);
            *reinterpret_cast<float2*>(C + (size_t)r1 * N + cn) = make_float2(v10, v11);
        }
    }
}

// =====================================================================
// Attention: one block = (b, h, 32 q rows), 512 threads.
// S[32][1024] scores in smem; K chunk stored d-major, V chunk k-major.
// =====================================================================
#define KV_LD  258     // [64][258] for K^T chunks (256 k cols + pad)
#define V_LD   66      // [256][66] for V chunks

__global__ __launch_bounds__(512) void attn_kernel(
    const float* __restrict__ Qp, const float* __restrict__ Kp,
    const float* __restrict__ Vp, const float* __restrict__ gate,
    const int* __restrict__ mask,
    float* __restrict__ attn, float* __restrict__ heads)
{
    extern __shared__ float sm[];
    float* S  = sm;                       // 32*1024
    float* Qs = S + 32 * 1024;            // 32*64
    float* KV = Qs + 32 * 64;             // max(64*258, 256*66) = 16896 floats

    const int b = blockIdx.z, h = blockIdx.y;
    const int q0 = blockIdx.x * 32;
    const int tid = threadIdx.x;

    // load Q tile [32][64]
    {
        int idx = tid;   // 512 float4 = 32*16
        int r = idx >> 4, c4 = (idx & 15) * 4;
        float4 qv = *reinterpret_cast<const float4*>(
            Qp + (size_t)(b * SEQ + q0 + r) * DM + h * DK + c4);
        *reinterpret_cast<float4*>(&Qs[r * 64 + c4]) = qv;
    }

    const int ty2 = tid >> 6;      // 0..7  (4-row q group)
    const int tx2 = tid & 63;      // k sub-col

    // ---- QK^T over 4 chunks of 256 k ----
    for (int kc = 0; kc < 4; kc++) {
        __syncthreads();
        // load K chunk transposed: KV[d][r] for r in [0,256)
        #pragma unroll
        for (int it = 0; it < 8; it++) {
            int idx = it * 512 + tid;          // 4096 float4
            int r = idx >> 4, c4 = (idx & 15) * 4;
            float4 kf = *reinterpret_cast<const float4*>(
                Kp + (size_t)(b * SEQ + kc * 256 + r) * DM + h * DK + c4);
            KV[(c4 + 0) * KV_LD + r] = kf.x;
            KV[(c4 + 1) * KV_LD + r] = kf.y;
            KV[(c4 + 2) * KV_LD + r] = kf.z;
            KV[(c4 + 3) * KV_LD + r] = kf.w;
        }
        __syncthreads();

        float acc[4][4];
        #pragma unroll
        for (int i = 0; i < 4; i++)
            #pragma unroll
            for (int j = 0; j < 4; j++) acc[i][j] = 0.f;

        for (int d0 = 0; d0 < 64; d0 += 4) {
            float4 qv[4];
            #pragma unroll
            for (int ii = 0; ii < 4; ii++)
                qv[ii] = *reinterpret_cast<const float4*>(&Qs[(ty2 * 4 + ii) * 64 + d0]);
            #pragma unroll
            for (int dj = 0; dj < 4; dj++) {
                float kv[4];
                #pragma unroll
                for (int jj = 0; jj < 4; jj++)
                    kv[jj] = KV[(d0 + dj) * KV_LD + tx2 + jj * 64];
                #pragma unroll
                for (int ii = 0; ii < 4; ii++) {
                    float q = (dj == 0) ? qv[ii].x : (dj == 1) ? qv[ii].y : (dj == 2) ? qv[ii].z : qv[ii].w;
                    #pragma unroll
                    for (int jj = 0; jj < 4; jj++)
                        acc[ii][jj] = fmaf(q, kv[jj], acc[ii][jj]);
                }
            }
        }
        #pragma unroll
        for (int ii = 0; ii < 4; ii++)
            #pragma unroll
            for (int jj = 0; jj < 4; jj++)
                S[(ty2 * 4 + ii) * 1024 + kc * 256 + tx2 + jj * 64] = acc[ii][jj];
    }
    __syncthreads();

    // ---- gate * scale, mask ----
    {
        const float inv_temp = 0.125f;
        #pragma unroll
        for (int it = 0; it < 16; it++) {
            int idx = it * 512 + tid;          // 8192 float4
            int r = idx >> 8, c4 = (idx & 255) * 4;
            float4 s4 = *reinterpret_cast<float4*>(&S[r * 1024 + c4]);
            float4 g4 = *reinterpret_cast<const float4*>(
                gate + ((size_t)(b * NHEAD + h) * SEQ + q0 + r) * SEQ + c4);
            int4 m4 = *reinterpret_cast<const int4*>(
                mask + ((size_t)(b * SEQ + q0 + r)) * SEQ + c4);
            s4.x = m4.x ? -INFINITY : s4.x * inv_temp * g4.x;
            s4.y = m4.y ? -INFINITY : s4.y * inv_temp * g4.y;
            s4.z = m4.z ? -INFINITY : s4.z * inv_temp * g4.z;
            s4.w = m4.w ? -INFINITY : s4.w * inv_temp * g4.w;
            *reinterpret_cast<float4*>(&S[r * 1024 + c4]) = s4;
        }
    }
    __syncthreads();

    // ---- softmax: warp per 2 rows; write probs to S and attn ----
    {
        const int wid = tid >> 5, lane = tid & 31;
        #pragma unroll
        for (int rr = 0; rr < 2; rr++) {
            int r = wid * 2 + rr;
            float* srow = S + r * 1024;
            float mx = -INFINITY;
            #pragma unroll
            for (int i = 0; i < 8; i++) {
                float4 v = *reinterpret_cast<float4*>(&srow[(lane + i * 32) * 4]);
                mx = fmaxf(mx, fmaxf(fmaxf(v.x, v.y), fmaxf(v.z, v.w)));
            }
            #pragma unroll
            for (int o = 16; o; o >>= 1) mx = fmaxf(mx, __shfl_xor_sync(0xffffffffu, mx, o));
            float sum = 0.f;
            #pragma unroll
            for (int i = 0; i < 8; i++) {
                float4 v = *reinterpret_cast<float4*>(&srow[(lane + i * 32) * 4]);
                v.x = __expf(v.x - mx); v.y = __expf(v.y - mx);
                v.z = __expf(v.z - mx); v.w = __expf(v.w - mx);
                sum += v.x + v.y + v.z + v.w;
                *reinterpret_cast<float4*>(&srow[(lane + i * 32) * 4]) = v;
            }
            #pragma unroll
            for (int o = 16; o; o >>= 1) sum += __shfl_xor_sync(0xffffffffu, sum, o);
            float inv = 1.f / sum;
            float* arow = attn + ((size_t)(b * NHEAD + h) * SEQ + q0 + r) * SEQ;
            #pragma unroll
            for (int i = 0; i < 8; i++) {
                float4 v = *reinterpret_cast<float4*>(&srow[(lane + i * 32) * 4]);
                v.x *= inv; v.y *= inv; v.z *= inv; v.w *= inv;
                *reinterpret_cast<float4*>(&srow[(lane + i * 32) * 4]) = v;
                *reinterpret_cast<float4*>(&arow[(lane + i * 32) * 4]) = v;
            }
        }
    }

    // ---- PV: out[32][64] = S @ V ----
    const int ty3 = tid >> 6;     // 0..7 (4-row group)
    const int dd  = tid & 63;     // d
    float oacc[4] = {0.f, 0.f, 0.f, 0.f};

    for (int kc = 0; kc < 4; kc++) {
        __syncthreads();
        // load V chunk k-major: KV[r][d], r in [0,256)
        #pragma unroll
        for (int it = 0; it < 8; it++) {
            int idx = it * 512 + tid;
            int r = idx >> 4, c4 = (idx & 15) * 4;
            float4 vf = *reinterpret_cast<const float4*>(
                Vp + (size_t)(b * SEQ + kc * 256 + r) * DM + h * DK + c4);
            KV[r * V_LD + c4 + 0] = vf.x;
            KV[r * V_LD + c4 + 1] = vf.y;
            KV[r * V_LD + c4 + 2] = vf.z;
            KV[r * V_LD + c4 + 3] = vf.w;
        }
        __syncthreads();

        for (int k4 = 0; k4 < 64; k4++) {
            float4 p4[4];
            #pragma unroll
            for (int ii = 0; ii < 4; ii++)
                p4[ii] = *reinterpret_cast<const float4*>(
                    &S[(ty3 * 4 + ii) * 1024 + kc * 256 + k4 * 4]);
            #pragma unroll
            for (int j = 0; j < 4; j++) {
                float v = KV[(k4 * 4 + j) * V_LD + dd];
                #pragma unroll
                for (int ii = 0; ii < 4; ii++) {
                    float p = (j == 0) ? p4[ii].x : (j == 1) ? p4[ii].y : (j == 2) ? p4[ii].z : p4[ii].w;
                    oacc[ii] = fmaf(p, v, oacc[ii]);
                }
            }
        }
    }

    #pragma unroll
    for (int ii = 0; ii < 4; ii++)
        heads[(size_t)(b * SEQ + q0 + ty3 * 4 + ii) * DM + h * DK + dd] = oacc[ii];
}

// ---------------- LayerNorm ----------------
__global__ __launch_bounds__(256) void ln_kernel(
    const float* __restrict__ X, const float* __restrict__ gamma,
    const float* __restrict__ beta, float* __restrict__ out)
{
    __shared__ float sh1[8];
    __shared__ float sh2[8];
    const int row = blockIdx.x;
    const int tid = threadIdx.x;
    const float* x = X + (size_t)row * DM;

    float v[4];
    float s = 0.f;
    #pragma unroll
    for (int i = 0; i < 4; i++) { v[i] = x[tid + i * 256]; s += v[i]; }
    #pragma unroll
    for (int o = 16; o; o >>= 1) s += __shfl_xor_sync(0xffffffffu, s, o);
    if ((tid & 31) == 0) sh1[tid >> 5] = s;
    __syncthreads();
    float tot = 0.f;
    #pragma unroll
    for (int w = 0; w < 8; w++) tot += sh1[w];
    float mu = tot * (1.f / DM);

    float vs = 0.f;
    #pragma unroll
    for (int i = 0; i < 4; i++) { float d = v[i] - mu; vs += d * d; }
    #pragma unroll
    for (int o = 16; o; o >>= 1) vs += __shfl_xor_sync(0xffffffffu, vs, o);
    if ((tid & 31) == 0) sh2[tid >> 5] = vs;
    __syncthreads();
    float tv = 0.f;
    #pragma unroll
    for (int w = 0; w < 8; w++) tv += sh2[w];
    float inv = rsqrtf(tv * (1.f / DM) + LN_EPS);

    float* orow = out + (size_t)row * DM;
    #pragma unroll
    for (int i = 0; i < 4; i++) {
        int c = tid + i * 256;
        orow[c] = (v[i] - mu) * inv * gamma[c] + beta[c];
    }
}

// ---------------- launch ----------------
extern "C" void kernel_launch(void* const* d_in, const int* in_sizes, int n_in,
                              void* d_out, int out_size)
{
    const float* q      = (const float*)d_in[0];
    const float* k      = (const float*)d_in[1];
    const float* v      = (const float*)d_in[2];
    const float* k_gate = (const float*)d_in[3];
    const int*   mask   = (const int*)d_in[4];
    const float* Wq = (const float*)d_in[5];
    const float* bq = (const float*)d_in[6];
    const float* Wk = (const float*)d_in[7];
    const float* bk = (const float*)d_in[8];
    const float* Wv = (const float*)d_in[9];
    const float* bv = (const float*)d_in[10];
    const float* Wo = (const float*)d_in[11];
    const float* bo = (const float*)d_in[12];
    const float* ln_g = (const float*)d_in[13];
    const float* ln_b = (const float*)d_in[14];

    float* out  = (float*)d_out;
    float* attn = out + (size_t)BATCH * SEQ * DM;

    float *Qp, *Kp, *Vp, *heads, *tmp;
    cudaGetSymbolAddress((void**)&Qp, g_Qp);
    cudaGetSymbolAddress((void**)&Kp, g_Kp);
    cudaGetSymbolAddress((void**)&Vp, g_Vp);
    cudaGetSymbolAddress((void**)&heads, g_heads);
    cudaGetSymbolAddress((void**)&tmp, g_tmp);

    const int ATTN_SMEM = (32 * 1024 + 32 * 64 + 16896) * (int)sizeof(float);  // 206848 B
    cudaFuncSetAttribute(attn_kernel, cudaFuncAttributeMaxDynamicSharedMemorySize, ATTN_SMEM);

    dim3 gblk(256);
    dim3 ggrid(DM / 128, MROWS / 128);   // (8, 32)

    tf32_gemm<<<ggrid, gblk>>>(q, Wq, bq, nullptr, Qp, MROWS, DM, DM);
    tf32_gemm<<<ggrid, gblk>>>(k, Wk, bk, nullptr, Kp, MROWS, DM, DM);
    tf32_gemm<<<ggrid, gblk>>>(v, Wv, bv, nullptr, Vp, MROWS, DM, DM);

    dim3 agrid(SEQ / 32, NHEAD, BATCH);
    attn_kernel<<<agrid, 512, ATTN_SMEM>>>(Qp, Kp, Vp, k_gate, mask, attn, heads);

    tf32_gemm<<<ggrid, gblk>>>(heads, Wo, bo, q, tmp, MROWS, DM, DM);

    ln_kernel<<<MROWS, 256>>>(tmp, ln_g, ln_b, out);
}

// round 5
// speedup vs baseline: 2.1625x; 1.4604x over previous
#include <cuda_runtime.h>
#include <cuda_bf16.h>
#include <cstdint>
#include <cmath>

#define BATCH   4
#define SEQ     1024
#define DM      1024
#define NHEAD   16
#define DK      64
#define MROWS   (BATCH*SEQ)
#define LN_EPS  1e-5f

__device__ float g_Qp[MROWS * DM];
__device__ float g_Kp[MROWS * DM];
__device__ float g_Vp[MROWS * DM];
__device__ float g_heads[MROWS * DM];
__device__ float g_tmp[MROWS * DM];

// ---------------- bf16 hi/lo split helpers ----------------
__device__ __forceinline__ void bsplit4(float4 v, uint2& h, uint2& l) {
    __nv_bfloat162 h0 = __floats2bfloat162_rn(v.x, v.y);
    __nv_bfloat162 h1 = __floats2bfloat162_rn(v.z, v.w);
    float r0 = v.x - __bfloat162float(h0.x);
    float r1 = v.y - __bfloat162float(h0.y);
    float r2 = v.z - __bfloat162float(h1.x);
    float r3 = v.w - __bfloat162float(h1.y);
    __nv_bfloat162 l0 = __floats2bfloat162_rn(r0, r1);
    __nv_bfloat162 l1 = __floats2bfloat162_rn(r2, r3);
    h.x = *reinterpret_cast<uint32_t*>(&h0);
    h.y = *reinterpret_cast<uint32_t*>(&h1);
    l.x = *reinterpret_cast<uint32_t*>(&l0);
    l.y = *reinterpret_cast<uint32_t*>(&l1);
}

__device__ __forceinline__ void bsplit2(float a, float b, uint32_t& h, uint32_t& l) {
    __nv_bfloat162 hh = __floats2bfloat162_rn(a, b);
    float ra = a - __bfloat162float(hh.x);
    float rb = b - __bfloat162float(hh.y);
    __nv_bfloat162 ll = __floats2bfloat162_rn(ra, rb);
    h = *reinterpret_cast<uint32_t*>(&hh);
    l = *reinterpret_cast<uint32_t*>(&ll);
}

__device__ __forceinline__ void mma_bf16(float* c, const uint32_t* a, const uint32_t* b) {
    asm volatile(
        "mma.sync.aligned.m16n8k16.row.col.f32.bf16.bf16.f32 "
        "{%0,%1,%2,%3}, {%4,%5,%6,%7}, {%8,%9}, {%0,%1,%2,%3};"
        : "+f"(c[0]), "+f"(c[1]), "+f"(c[2]), "+f"(c[3])
        : "r"(a[0]), "r"(a[1]), "r"(a[2]), "r"(a[3]), "r"(b[0]), "r"(b[1]));
}

// =====================================================================
// bf16x3 GEMM: C = A @ W^T + bias (+resid).  BM=128, BN=64, BK=32.
// =====================================================================
#define GW 20

__device__ __forceinline__ void gemm_core(
    const float* __restrict__ A, const float* __restrict__ W,
    const float* __restrict__ bias, const float* __restrict__ resid,
    float* __restrict__ C, int bm, int bn)
{
    __shared__ uint32_t AsH[128 * GW], AsL[128 * GW];
    __shared__ uint32_t BsH[64 * GW],  BsL[64 * GW];

    const int tid = threadIdx.x;
    const int wid = tid >> 5, lane = tid & 31;
    const int g = lane >> 2, t = lane & 3;
    const int warpM = (wid & 1) * 64;
    const int warpN = (wid >> 1) * 16;

    float c[4][2][4];
    #pragma unroll
    for (int mt = 0; mt < 4; mt++)
        #pragma unroll
        for (int nt = 0; nt < 2; nt++)
            #pragma unroll
            for (int i = 0; i < 4; i++) c[mt][nt][i] = 0.f;

    for (int k0 = 0; k0 < DM; k0 += 32) {
        float4 sa[4], sb[2];
        #pragma unroll
        for (int it = 0; it < 4; it++) {
            int idx = it * 256 + tid;
            int r = idx >> 3, c4 = (idx & 7) * 4;
            sa[it] = *reinterpret_cast<const float4*>(A + (size_t)(bm + r) * DM + k0 + c4);
        }
        #pragma unroll
        for (int it = 0; it < 2; it++) {
            int idx = it * 256 + tid;
            int r = idx >> 3, c4 = (idx & 7) * 4;
            sb[it] = *reinterpret_cast<const float4*>(W + (size_t)(bn + r) * DM + k0 + c4);
        }
        __syncthreads();
        #pragma unroll
        for (int it = 0; it < 4; it++) {
            int idx = it * 256 + tid;
            int r = idx >> 3, w = (idx & 7) * 2;
            uint2 h, l; bsplit4(sa[it], h, l);
            *reinterpret_cast<uint2*>(&AsH[r * GW + w]) = h;
            *reinterpret_cast<uint2*>(&AsL[r * GW + w]) = l;
        }
        #pragma unroll
        for (int it = 0; it < 2; it++) {
            int idx = it * 256 + tid;
            int r = idx >> 3, w = (idx & 7) * 2;
            uint2 h, l; bsplit4(sb[it], h, l);
            *reinterpret_cast<uint2*>(&BsH[r * GW + w]) = h;
            *reinterpret_cast<uint2*>(&BsL[r * GW + w]) = l;
        }
        __syncthreads();

        #pragma unroll
        for (int ks = 0; ks < 2; ks++) {
            int kk2 = ks * 8;
            uint32_t aH[4][4], aL[4][4], bH[2][2], bL[2][2];
            #pragma unroll
            for (int mt = 0; mt < 4; mt++) {
                int base = (warpM + mt * 16 + g) * GW + kk2 + t;
                aH[mt][0] = AsH[base];          aH[mt][1] = AsH[base + 8 * GW];
                aH[mt][2] = AsH[base + 4];      aH[mt][3] = AsH[base + 8 * GW + 4];
                aL[mt][0] = AsL[base];          aL[mt][1] = AsL[base + 8 * GW];
                aL[mt][2] = AsL[base + 4];      aL[mt][3] = AsL[base + 8 * GW + 4];
            }
            #pragma unroll
            for (int nt = 0; nt < 2; nt++) {
                int base = (warpN + nt * 8 + g) * GW + kk2 + t;
                bH[nt][0] = BsH[base]; bH[nt][1] = BsH[base + 4];
                bL[nt][0] = BsL[base]; bL[nt][1] = BsL[base + 4];
            }
            #pragma unroll
            for (int mt = 0; mt < 4; mt++)
                #pragma unroll
                for (int nt = 0; nt < 2; nt++) {
                    mma_bf16(c[mt][nt], aH[mt], bH[nt]);
                    mma_bf16(c[mt][nt], aH[mt], bL[nt]);
                    mma_bf16(c[mt][nt], aL[mt], bH[nt]);
                }
        }
        __syncthreads();
    }

    #pragma unroll
    for (int mt = 0; mt < 4; mt++) {
        int r0 = bm + warpM + mt * 16 + g;
        int r1 = r0 + 8;
        #pragma unroll
        for (int nt = 0; nt < 2; nt++) {
            int cn = bn + warpN + nt * 8 + 2 * t;
            float b0 = bias[cn], b1 = bias[cn + 1];
            float v00 = c[mt][nt][0] + b0, v01 = c[mt][nt][1] + b1;
            float v10 = c[mt][nt][2] + b0, v11 = c[mt][nt][3] + b1;
            if (resid) {
                float2 rA = *reinterpret_cast<const float2*>(resid + (size_t)r0 * DM + cn);
                float2 rB = *reinterpret_cast<const float2*>(resid + (size_t)r1 * DM + cn);
                v00 += rA.x; v01 += rA.y; v10 += rB.x; v11 += rB.y;
            }
            *reinterpret_cast<float2*>(C + (size_t)r0 * DM + cn) = make_float2(v00, v01);
            *reinterpret_cast<float2*>(C + (size_t)r1 * DM + cn) = make_float2(v10, v11);
        }
    }
}

__global__ __launch_bounds__(256) void qkv_gemm(
    const float* __restrict__ q, const float* __restrict__ k, const float* __restrict__ v,
    const float* __restrict__ Wq, const float* __restrict__ Wk, const float* __restrict__ Wv,
    const float* __restrict__ bq, const float* __restrict__ bk, const float* __restrict__ bv,
    float* __restrict__ Qp, float* __restrict__ Kp, float* __restrict__ Vp)
{
    const int z = blockIdx.z;
    const float* A = (z == 0) ? q : (z == 1) ? k : v;
    const float* W = (z == 0) ? Wq : (z == 1) ? Wk : Wv;
    const float* B = (z == 0) ? bq : (z == 1) ? bk : bv;
    float* C = (z == 0) ? Qp : (z == 1) ? Kp : Vp;
    gemm_core(A, W, B, nullptr, C, blockIdx.y * 128, blockIdx.x * 64);
}

__global__ __launch_bounds__(256) void out_gemm(
    const float* __restrict__ A, const float* __restrict__ W,
    const float* __restrict__ bias, const float* __restrict__ resid,
    float* __restrict__ C)
{
    gemm_core(A, W, bias, resid, C, blockIdx.y * 128, blockIdx.x * 64);
}

// =====================================================================
// Attention: block = (b, h, 32 q rows), 256 threads (8 warps).
// QK^T and PV on bf16x3 mma; S[32][1028] fp32 in smem.
// K stored [kv][d] (B operand, n=kv); V stored TRANSPOSED [d][kv] (n=d).
// =====================================================================
#define SLD 1028
#define LW  36      // words per row, Q/K/P tiles ([row][32 k-words] + pad)
#define VW  35      // words per d-row for transposed V
#define OFF_S   0
#define SZ_S    (32 * SLD * 4)
#define OFF_QP  SZ_S
#define SZ_QP   18432
#define OFF_KV  (OFF_QP + SZ_QP)
#define SZ_KV   36864
#define ATTN_SMEM_BYTES (OFF_KV + SZ_KV)

// transpose-store one float4 of V (thread holds V[kv][c4..c4+3]) into
// d-major bf16x2 hi/lo planes. Pairs lane <-> lane^16 hold kv, kv^1.
__device__ __forceinline__ void vt_store(uint32_t* VTH, uint32_t* VTL,
                                         float4 v, int kv, int c4, int lane)
{
    float4 p;
    p.x = __shfl_xor_sync(0xffffffffu, v.x, 16);
    p.y = __shfl_xor_sync(0xffffffffu, v.y, 16);
    p.z = __shfl_xor_sync(0xffffffffu, v.z, 16);
    p.w = __shfl_xor_sync(0xffffffffu, v.w, 16);
    int kvp = kv >> 1;
    float e0, o0, e1, o1;
    int d0;
    if ((lane & 16) == 0) { e0 = v.x; o0 = p.x; e1 = v.y; o1 = p.y; d0 = c4; }
    else                  { e0 = p.z; o0 = v.z; e1 = p.w; o1 = v.w; d0 = c4 + 2; }
    uint32_t h, l;
    bsplit2(e0, o0, h, l);
    VTH[d0 * VW + kvp] = h;  VTL[d0 * VW + kvp] = l;
    bsplit2(e1, o1, h, l);
    VTH[(d0 + 1) * VW + kvp] = h;  VTL[(d0 + 1) * VW + kvp] = l;
}

__global__ __launch_bounds__(256) void attn_kernel(
    const float* __restrict__ Qp, const float* __restrict__ Kp,
    const float* __restrict__ Vp, const float* __restrict__ gate,
    const int* __restrict__ mask,
    float* __restrict__ attn, float* __restrict__ heads)
{
    extern __shared__ char smraw[];
    float* S = reinterpret_cast<float*>(smraw + OFF_S);
    uint32_t* QH = reinterpret_cast<uint32_t*>(smraw + OFF_QP);
    uint32_t* QL = QH + 32 * LW;
    uint32_t* KVb = reinterpret_cast<uint32_t*>(smraw + OFF_KV);

    const int b = blockIdx.z, h = blockIdx.y;
    const int q0 = blockIdx.x * 32;
    const int tid = threadIdx.x;
    const int wid = tid >> 5, lane = tid & 31;
    const int g = lane >> 2, t = lane & 3;
    const int n = wid * 8;

    // ---- load Q tile [32][64] -> bf16 hi/lo ----
    #pragma unroll
    for (int it = 0; it < 2; it++) {
        int idx = it * 256 + tid;
        int r = idx >> 4, c4 = (idx & 15) * 4;
        float4 v = *reinterpret_cast<const float4*>(
            Qp + (size_t)(b * SEQ + q0 + r) * DM + h * DK + c4);
        uint2 hh, ll; bsplit4(v, hh, ll);
        *reinterpret_cast<uint2*>(&QH[r * LW + (c4 >> 1)]) = hh;
        *reinterpret_cast<uint2*>(&QL[r * LW + (c4 >> 1)]) = ll;
    }

    // ---- prologue: K chunk 0 -> buf 0 ----
    {
        uint32_t* KH = KVb;            uint32_t* KL = KVb + 2304;
        #pragma unroll
        for (int it = 0; it < 4; it++) {
            int idx = it * 256 + tid;
            int r = idx >> 4, c4 = (idx & 15) * 4;
            float4 v = *reinterpret_cast<const float4*>(
                Kp + (size_t)(b * SEQ + r) * DM + h * DK + c4);
            uint2 hh, ll; bsplit4(v, hh, ll);
            *reinterpret_cast<uint2*>(&KH[r * LW + (c4 >> 1)]) = hh;
            *reinterpret_cast<uint2*>(&KL[r * LW + (c4 >> 1)]) = ll;
        }
    }
    __syncthreads();

    const float inv_temp = 0.125f;

    // ---- QK^T: 16 chunks of 64 kv ----
    for (int kc = 0; kc < 16; kc++) {
        int buf = kc & 1;
        uint32_t* KH = KVb + buf * 4608;
        uint32_t* KL = KH + 2304;

        float4 stage[4];
        if (kc < 15) {
            #pragma unroll
            for (int it = 0; it < 4; it++) {
                int idx = it * 256 + tid;
                int r = idx >> 4, c4 = (idx & 15) * 4;
                stage[it] = *reinterpret_cast<const float4*>(
                    Kp + (size_t)(b * SEQ + (kc + 1) * 64 + r) * DM + h * DK + c4);
            }
        }

        float c0[2][4];
        #pragma unroll
        for (int mt = 0; mt < 2; mt++)
            #pragma unroll
            for (int i = 0; i < 4; i++) c0[mt][i] = 0.f;

        #pragma unroll
        for (int ks = 0; ks < 4; ks++) {
            int kk2 = ks * 8;
            uint32_t aH[2][4], aL[2][4], bH[2], bL[2];
            #pragma unroll
            for (int mt = 0; mt < 2; mt++) {
                int base = (mt * 16 + g) * LW + kk2 + t;
                aH[mt][0] = QH[base];     aH[mt][1] = QH[base + 8 * LW];
                aH[mt][2] = QH[base + 4]; aH[mt][3] = QH[base + 8 * LW + 4];
                aL[mt][0] = QL[base];     aL[mt][1] = QL[base + 8 * LW];
                aL[mt][2] = QL[base + 4]; aL[mt][3] = QL[base + 8 * LW + 4];
            }
            int bb = (n + g) * LW + kk2 + t;
            bH[0] = KH[bb]; bH[1] = KH[bb + 4];
            bL[0] = KL[bb]; bL[1] = KL[bb + 4];
            #pragma unroll
            for (int mt = 0; mt < 2; mt++) {
                mma_bf16(c0[mt], aH[mt], bH);
                mma_bf16(c0[mt], aH[mt], bL);
                mma_bf16(c0[mt], aL[mt], bH);
            }
        }

        // epilogue: gate * scale, mask, -> S
        #pragma unroll
        for (int mt = 0; mt < 2; mt++) {
            int col = kc * 64 + n + 2 * t;
            #pragma unroll
            for (int half = 0; half < 2; half++) {
                int q = mt * 16 + g + half * 8;
                const float2 gv = *reinterpret_cast<const float2*>(
                    gate + ((size_t)(b * NHEAD + h) * SEQ + q0 + q) * SEQ + col);
                const int2 mv = *reinterpret_cast<const int2*>(
                    mask + ((size_t)(b * SEQ + q0 + q)) * SEQ + col);
                float s0 = mv.x ? -INFINITY : c0[mt][half * 2 + 0] * inv_temp * gv.x;
                float s1 = mv.y ? -INFINITY : c0[mt][half * 2 + 1] * inv_temp * gv.y;
                *reinterpret_cast<float2*>(&S[q * SLD + col]) = make_float2(s0, s1);
            }
        }

        if (kc < 15) {
            uint32_t* NH = KVb + (buf ^ 1) * 4608;
            uint32_t* NL = NH + 2304;
            #pragma unroll
            for (int it = 0; it < 4; it++) {
                int idx = it * 256 + tid;
                int r = idx >> 4, c4 = (idx & 15) * 4;
                uint2 hh, ll; bsplit4(stage[it], hh, ll);
                *reinterpret_cast<uint2*>(&NH[r * LW + (c4 >> 1)]) = hh;
                *reinterpret_cast<uint2*>(&NL[r * LW + (c4 >> 1)]) = ll;
            }
        }
        __syncthreads();
    }

    // ---- softmax: 8 warps x 4 rows; write probs to S and attn ----
    #pragma unroll
    for (int rr = 0; rr < 4; rr++) {
        int r = wid * 4 + rr;
        float* srow = S + r * SLD;
        float mx = -INFINITY;
        #pragma unroll
        for (int i = 0; i < 8; i++) {
            float4 v = *reinterpret_cast<float4*>(&srow[(lane + i * 32) * 4]);
            mx = fmaxf(mx, fmaxf(fmaxf(v.x, v.y), fmaxf(v.z, v.w)));
        }
        #pragma unroll
        for (int o = 16; o; o >>= 1) mx = fmaxf(mx, __shfl_xor_sync(0xffffffffu, mx, o));
        float sum = 0.f;
        #pragma unroll
        for (int i = 0; i < 8; i++) {
            float4 v = *reinterpret_cast<float4*>(&srow[(lane + i * 32) * 4]);
            v.x = __expf(v.x - mx); v.y = __expf(v.y - mx);
            v.z = __expf(v.z - mx); v.w = __expf(v.w - mx);
            sum += v.x + v.y + v.z + v.w;
            *reinterpret_cast<float4*>(&srow[(lane + i * 32) * 4]) = v;
        }
        #pragma unroll
        for (int o = 16; o; o >>= 1) sum += __shfl_xor_sync(0xffffffffu, sum, o);
        float inv = 1.f / sum;
        float* arow = attn + ((size_t)(b * NHEAD + h) * SEQ + q0 + r) * SEQ;
        #pragma unroll
        for (int i = 0; i < 8; i++) {
            float4 v = *reinterpret_cast<float4*>(&srow[(lane + i * 32) * 4]);
            v.x *= inv; v.y *= inv; v.z *= inv; v.w *= inv;
            *reinterpret_cast<float4*>(&srow[(lane + i * 32) * 4]) = v;
            *reinterpret_cast<float4*>(&arow[(lane + i * 32) * 4]) = v;
        }
    }
    __syncthreads();

    // ---- PV: 16 chunks of 64 kv. V transposed to [d][kv] in smem. ----
    {
        uint32_t* VTH = KVb;            uint32_t* VTL = KVb + 2304;
        uint32_t* PH = reinterpret_cast<uint32_t*>(smraw + OFF_QP);
        uint32_t* PL = PH + 32 * LW;
        #pragma unroll
        for (int it = 0; it < 4; it++) {
            int idx = it * 256 + tid;
            int kv = idx >> 4, c4 = (idx & 15) * 4;
            float4 v = *reinterpret_cast<const float4*>(
                Vp + (size_t)(b * SEQ + kv) * DM + h * DK + c4);
            vt_store(VTH, VTL, v, kv, c4, lane);
        }
        #pragma unroll
        for (int it = 0; it < 2; it++) {
            int idx = it * 256 + tid;
            int r = idx >> 4, c4 = (idx & 15) * 4;
            float4 v = *reinterpret_cast<const float4*>(&S[r * SLD + c4]);
            uint2 hh, ll; bsplit4(v, hh, ll);
            *reinterpret_cast<uint2*>(&PH[r * LW + (c4 >> 1)]) = hh;
            *reinterpret_cast<uint2*>(&PL[r * LW + (c4 >> 1)]) = ll;
        }
    }
    __syncthreads();

    float o[2][4];
    #pragma unroll
    for (int mt = 0; mt < 2; mt++)
        #pragma unroll
        for (int i = 0; i < 4; i++) o[mt][i] = 0.f;

    for (int kc = 0; kc < 16; kc++) {
        int buf = kc & 1;
        uint32_t* VTH = KVb + buf * 4608;
        uint32_t* VTL = VTH + 2304;
        uint32_t* PH = reinterpret_cast<uint32_t*>(smraw + OFF_QP) + buf * 2304;
        uint32_t* PL = PH + 32 * LW;

        float4 vstage[4], pstage[2];
        if (kc < 15) {
            #pragma unroll
            for (int it = 0; it < 4; it++) {
                int idx = it * 256 + tid;
                int kv = idx >> 4, c4 = (idx & 15) * 4;
                vstage[it] = *reinterpret_cast<const float4*>(
                    Vp + (size_t)(b * SEQ + (kc + 1) * 64 + kv) * DM + h * DK + c4);
            }
            #pragma unroll
            for (int it = 0; it < 2; it++) {
                int idx = it * 256 + tid;
                int r = idx >> 4, c4 = (idx & 15) * 4;
                pstage[it] = *reinterpret_cast<const float4*>(&S[r * SLD + (kc + 1) * 64 + c4]);
            }
        }

        #pragma unroll
        for (int ks = 0; ks < 4; ks++) {
            int kk2 = ks * 8;
            uint32_t aH[2][4], aL[2][4], bH[2], bL[2];
            #pragma unroll
            for (int mt = 0; mt < 2; mt++) {
                int base = (mt * 16 + g) * LW + kk2 + t;
                aH[mt][0] = PH[base];     aH[mt][1] = PH[base + 8 * LW];
                aH[mt][2] = PH[base + 4]; aH[mt][3] = PH[base + 8 * LW + 4];
                aL[mt][0] = PL[base];     aL[mt][1] = PL[base + 8 * LW];
                aL[mt][2] = PL[base + 4]; aL[mt][3] = PL[base + 8 * LW + 4];
            }
            int bb = (n + g) * VW + kk2 + t;   // B = V^T: [n=d][k=kv]
            bH[0] = VTH[bb]; bH[1] = VTH[bb + 4];
            bL[0] = VTL[bb]; bL[1] = VTL[bb + 4];
            #pragma unroll
            for (int mt = 0; mt < 2; mt++) {
                mma_bf16(o[mt], aH[mt], bH);
                mma_bf16(o[mt], aH[mt], bL);
                mma_bf16(o[mt], aL[mt], bH);
            }
        }

        if (kc < 15) {
            uint32_t* NVH = KVb + (buf ^ 1) * 4608;
            uint32_t* NVL = NVH + 2304;
            uint32_t* NPH = reinterpret_cast<uint32_t*>(smraw + OFF_QP) + (buf ^ 1) * 2304;
            uint32_t* NPL = NPH + 32 * LW;
            #pragma unroll
            for (int it = 0; it < 4; it++) {
                int idx = it * 256 + tid;
                int kv = idx >> 4, c4 = (idx & 15) * 4;
                vt_store(NVH, NVL, vstage[it], kv, c4, lane);
            }
            #pragma unroll
            for (int it = 0; it < 2; it++) {
                int idx = it * 256 + tid;
                int r = idx >> 4, c4 = (idx & 15) * 4;
                uint2 hh, ll; bsplit4(pstage[it], hh, ll);
                *reinterpret_cast<uint2*>(&NPH[r * LW + (c4 >> 1)]) = hh;
                *reinterpret_cast<uint2*>(&NPL[r * LW + (c4 >> 1)]) = ll;
            }
        }
        __syncthreads();
    }

    // write heads
    #pragma unroll
    for (int mt = 0; mt < 2; mt++) {
        int d = n + 2 * t;
        int qA = q0 + mt * 16 + g;
        int qB = qA + 8;
        *reinterpret_cast<float2*>(heads + (size_t)(b * SEQ + qA) * DM + h * DK + d) =
            make_float2(o[mt][0], o[mt][1]);
        *reinterpret_cast<float2*>(heads + (size_t)(b * SEQ + qB) * DM + h * DK + d) =
            make_float2(o[mt][2], o[mt][3]);
    }
}

// ---------------- LayerNorm ----------------
__global__ __launch_bounds__(256) void ln_kernel(
    const float* __restrict__ X, const float* __restrict__ gamma,
    const float* __restrict__ beta, float* __restrict__ out)
{
    __shared__ float sh1[8];
    __shared__ float sh2[8];
    const int row = blockIdx.x;
    const int tid = threadIdx.x;
    const float* x = X + (size_t)row * DM;

    float v[4];
    float s = 0.f;
    #pragma unroll
    for (int i = 0; i < 4; i++) { v[i] = x[tid + i * 256]; s += v[i]; }
    #pragma unroll
    for (int o = 16; o; o >>= 1) s += __shfl_xor_sync(0xffffffffu, s, o);
    if ((tid & 31) == 0) sh1[tid >> 5] = s;
    __syncthreads();
    float tot = 0.f;
    #pragma unroll
    for (int w = 0; w < 8; w++) tot += sh1[w];
    float mu = tot * (1.f / DM);

    float vs = 0.f;
    #pragma unroll
    for (int i = 0; i < 4; i++) { float d = v[i] - mu; vs += d * d; }
    #pragma unroll
    for (int o = 16; o; o >>= 1) vs += __shfl_xor_sync(0xffffffffu, vs, o);
    if ((tid & 31) == 0) sh2[tid >> 5] = vs;
    __syncthreads();
    float tv = 0.f;
    #pragma unroll
    for (int w = 0; w < 8; w++) tv += sh2[w];
    float inv = rsqrtf(tv * (1.f / DM) + LN_EPS);

    float* orow = out + (size_t)row * DM;
    #pragma unroll
    for (int i = 0; i < 4; i++) {
        int c = tid + i * 256;
        orow[c] = (v[i] - mu) * inv * gamma[c] + beta[c];
    }
}

// ---------------- launch ----------------
extern "C" void kernel_launch(void* const* d_in, const int* in_sizes, int n_in,
                              void* d_out, int out_size)
{
    const float* q      = (const float*)d_in[0];
    const float* k      = (const float*)d_in[1];
    const float* v      = (const float*)d_in[2];
    const float* k_gate = (const float*)d_in[3];
    const int*   mask   = (const int*)d_in[4];
    const float* Wq = (const float*)d_in[5];
    const float* bq = (const float*)d_in[6];
    const float* Wk = (const float*)d_in[7];
    const float* bk = (const float*)d_in[8];
    const float* Wv = (const float*)d_in[9];
    const float* bv = (const float*)d_in[10];
    const float* Wo = (const float*)d_in[11];
    const float* bo = (const float*)d_in[12];
    const float* ln_g = (const float*)d_in[13];
    const float* ln_b = (const float*)d_in[14];

    float* out  = (float*)d_out;
    float* attn = out + (size_t)BATCH * SEQ * DM;

    float *Qp, *Kp, *Vp, *heads, *tmp;
    cudaGetSymbolAddress((void**)&Qp, g_Qp);
    cudaGetSymbolAddress((void**)&Kp, g_Kp);
    cudaGetSymbolAddress((void**)&Vp, g_Vp);
    cudaGetSymbolAddress((void**)&heads, g_heads);
    cudaGetSymbolAddress((void**)&tmp, g_tmp);

    cudaFuncSetAttribute(attn_kernel, cudaFuncAttributeMaxDynamicSharedMemorySize,
                         ATTN_SMEM_BYTES);

    dim3 qkvgrid(DM / 64, MROWS / 128, 3);
    qkv_gemm<<<qkvgrid, 256>>>(q, k, v, Wq, Wk, Wv, bq, bk, bv, Qp, Kp, Vp);

    dim3 agrid(SEQ / 32, NHEAD, BATCH);
    attn_kernel<<<agrid, 256, ATTN_SMEM_BYTES>>>(Qp, Kp, Vp, k_gate, mask, attn, heads);

    dim3 ogrid(DM / 64, MROWS / 128);
    out_gemm<<<ogrid, 256>>>(heads, Wo, bo, q, tmp);

    ln_kernel<<<MROWS, 256>>>(tmp, ln_g, ln_b, out);
}

// round 6
// speedup vs baseline: 2.5101x; 1.1607x over previous
#include <cuda_runtime.h>
#include <cuda_bf16.h>
#include <cstdint>
#include <cmath>

#define BATCH   4
#define SEQ     1024
#define DM      1024
#define NHEAD   16
#define DK      64
#define MROWS   (BATCH*SEQ)
#define LN_EPS  1e-5f

__device__ float g_Qp[MROWS * DM];
__device__ float g_Kp[MROWS * DM];
__device__ float g_Vp[MROWS * DM];
__device__ float g_heads[MROWS * DM];
__device__ float g_tmp[MROWS * DM];

// ---------------- bf16 hi/lo split helpers ----------------
__device__ __forceinline__ void bsplit4(float4 v, uint2& h, uint2& l) {
    __nv_bfloat162 h0 = __floats2bfloat162_rn(v.x, v.y);
    __nv_bfloat162 h1 = __floats2bfloat162_rn(v.z, v.w);
    float r0 = v.x - __bfloat162float(h0.x);
    float r1 = v.y - __bfloat162float(h0.y);
    float r2 = v.z - __bfloat162float(h1.x);
    float r3 = v.w - __bfloat162float(h1.y);
    __nv_bfloat162 l0 = __floats2bfloat162_rn(r0, r1);
    __nv_bfloat162 l1 = __floats2bfloat162_rn(r2, r3);
    h.x = *reinterpret_cast<uint32_t*>(&h0);
    h.y = *reinterpret_cast<uint32_t*>(&h1);
    l.x = *reinterpret_cast<uint32_t*>(&l0);
    l.y = *reinterpret_cast<uint32_t*>(&l1);
}

__device__ __forceinline__ void bsplit2(float a, float b, uint32_t& h, uint32_t& l) {
    __nv_bfloat162 hh = __floats2bfloat162_rn(a, b);
    float ra = a - __bfloat162float(hh.x);
    float rb = b - __bfloat162float(hh.y);
    __nv_bfloat162 ll = __floats2bfloat162_rn(ra, rb);
    h = *reinterpret_cast<uint32_t*>(&hh);
    l = *reinterpret_cast<uint32_t*>(&ll);
}

__device__ __forceinline__ void mma_bf16(float* c, const uint32_t* a, const uint32_t* b) {
    asm volatile(
        "mma.sync.aligned.m16n8k16.row.col.f32.bf16.bf16.f32 "
        "{%0,%1,%2,%3}, {%4,%5,%6,%7}, {%8,%9}, {%0,%1,%2,%3};"
        : "+f"(c[0]), "+f"(c[1]), "+f"(c[2]), "+f"(c[3])
        : "r"(a[0]), "r"(a[1]), "r"(a[2]), "r"(a[3]), "r"(b[0]), "r"(b[1]));
}

// =====================================================================
// bf16x3 GEMM: C = A @ W^T + bias (+resid).  BM=128, BN=64, BK=32.
// Software-pipelined: next-tile LDGs issued before compute (regs freed by store).
// =====================================================================
#define GW 20

#define GEMM_LOAD(k0) do { \
    _Pragma("unroll") \
    for (int it = 0; it < 4; it++) { \
        int idx = it * 256 + tid; int r = idx >> 3, c4 = (idx & 7) * 4; \
        sa[it] = *reinterpret_cast<const float4*>(A + (size_t)(bm + r) * DM + (k0) + c4); \
    } \
    _Pragma("unroll") \
    for (int it = 0; it < 2; it++) { \
        int idx = it * 256 + tid; int r = idx >> 3, c4 = (idx & 7) * 4; \
        sb[it] = *reinterpret_cast<const float4*>(W + (size_t)(bn + r) * DM + (k0) + c4); \
    } \
} while (0)

__device__ __forceinline__ void gemm_core(
    const float* __restrict__ A, const float* __restrict__ W,
    const float* __restrict__ bias, const float* __restrict__ resid,
    float* __restrict__ C, int bm, int bn)
{
    __shared__ uint32_t AsH[128 * GW], AsL[128 * GW];
    __shared__ uint32_t BsH[64 * GW],  BsL[64 * GW];

    const int tid = threadIdx.x;
    const int wid = tid >> 5, lane = tid & 31;
    const int g = lane >> 2, t = lane & 3;
    const int warpM = (wid & 1) * 64;
    const int warpN = (wid >> 1) * 16;

    float c[4][2][4];
    #pragma unroll
    for (int mt = 0; mt < 4; mt++)
        #pragma unroll
        for (int nt = 0; nt < 2; nt++)
            #pragma unroll
            for (int i = 0; i < 4; i++) c[mt][nt][i] = 0.f;

    float4 sa[4], sb[2];
    GEMM_LOAD(0);

    for (int k0 = 0; k0 < DM; k0 += 32) {
        __syncthreads();
        #pragma unroll
        for (int it = 0; it < 4; it++) {
            int idx = it * 256 + tid;
            int r = idx >> 3, w = (idx & 7) * 2;
            uint2 h, l; bsplit4(sa[it], h, l);
            *reinterpret_cast<uint2*>(&AsH[r * GW + w]) = h;
            *reinterpret_cast<uint2*>(&AsL[r * GW + w]) = l;
        }
        #pragma unroll
        for (int it = 0; it < 2; it++) {
            int idx = it * 256 + tid;
            int r = idx >> 3, w = (idx & 7) * 2;
            uint2 h, l; bsplit4(sb[it], h, l);
            *reinterpret_cast<uint2*>(&BsH[r * GW + w]) = h;
            *reinterpret_cast<uint2*>(&BsL[r * GW + w]) = l;
        }
        __syncthreads();

        if (k0 + 32 < DM) GEMM_LOAD(k0 + 32);   // overlap with compute below

        #pragma unroll
        for (int ks = 0; ks < 2; ks++) {
            int kk2 = ks * 8;
            uint32_t aH[4][4], aL[4][4], bH[2][2], bL[2][2];
            #pragma unroll
            for (int mt = 0; mt < 4; mt++) {
                int base = (warpM + mt * 16 + g) * GW + kk2 + t;
                aH[mt][0] = AsH[base];          aH[mt][1] = AsH[base + 8 * GW];
                aH[mt][2] = AsH[base + 4];      aH[mt][3] = AsH[base + 8 * GW + 4];
                aL[mt][0] = AsL[base];          aL[mt][1] = AsL[base + 8 * GW];
                aL[mt][2] = AsL[base + 4];      aL[mt][3] = AsL[base + 8 * GW + 4];
            }
            #pragma unroll
            for (int nt = 0; nt < 2; nt++) {
                int base = (warpN + nt * 8 + g) * GW + kk2 + t;
                bH[nt][0] = BsH[base]; bH[nt][1] = BsH[base + 4];
                bL[nt][0] = BsL[base]; bL[nt][1] = BsL[base + 4];
            }
            #pragma unroll
            for (int mt = 0; mt < 4; mt++)
                #pragma unroll
                for (int nt = 0; nt < 2; nt++) {
                    mma_bf16(c[mt][nt], aH[mt], bH[nt]);
                    mma_bf16(c[mt][nt], aH[mt], bL[nt]);
                    mma_bf16(c[mt][nt], aL[mt], bH[nt]);
                }
        }
    }

    #pragma unroll
    for (int mt = 0; mt < 4; mt++) {
        int r0 = bm + warpM + mt * 16 + g;
        int r1 = r0 + 8;
        #pragma unroll
        for (int nt = 0; nt < 2; nt++) {
            int cn = bn + warpN + nt * 8 + 2 * t;
            float b0 = bias[cn], b1 = bias[cn + 1];
            float v00 = c[mt][nt][0] + b0, v01 = c[mt][nt][1] + b1;
            float v10 = c[mt][nt][2] + b0, v11 = c[mt][nt][3] + b1;
            if (resid) {
                float2 rA = *reinterpret_cast<const float2*>(resid + (size_t)r0 * DM + cn);
                float2 rB = *reinterpret_cast<const float2*>(resid + (size_t)r1 * DM + cn);
                v00 += rA.x; v01 += rA.y; v10 += rB.x; v11 += rB.y;
            }
            *reinterpret_cast<float2*>(C + (size_t)r0 * DM + cn) = make_float2(v00, v01);
            *reinterpret_cast<float2*>(C + (size_t)r1 * DM + cn) = make_float2(v10, v11);
        }
    }
}

__global__ __launch_bounds__(256) void qkv_gemm(
    const float* __restrict__ q, const float* __restrict__ k, const float* __restrict__ v,
    const float* __restrict__ Wq, const float* __restrict__ Wk, const float* __restrict__ Wv,
    const float* __restrict__ bq, const float* __restrict__ bk, const float* __restrict__ bv,
    float* __restrict__ Qp, float* __restrict__ Kp, float* __restrict__ Vp)
{
    const int z = blockIdx.z;
    const float* A = (z == 0) ? q : (z == 1) ? k : v;
    const float* W = (z == 0) ? Wq : (z == 1) ? Wk : Wv;
    const float* B = (z == 0) ? bq : (z == 1) ? bk : bv;
    float* C = (z == 0) ? Qp : (z == 1) ? Kp : Vp;
    gemm_core(A, W, B, nullptr, C, blockIdx.y * 128, blockIdx.x * 64);
}

__global__ __launch_bounds__(256) void out_gemm(
    const float* __restrict__ A, const float* __restrict__ W,
    const float* __restrict__ bias, const float* __restrict__ resid,
    float* __restrict__ C)
{
    gemm_core(A, W, bias, resid, C, blockIdx.y * 128, blockIdx.x * 64);
}

// =====================================================================
// Attention QK + softmax: block = (b, h, 32 q rows), 256 threads.
// Probs written to global attn buffer; PV done by pv_gemm afterwards.
// =====================================================================
#define SLD 1028
#define LW  36
#define VW  35
#define OFF_S   0
#define SZ_S    (32 * SLD * 4)                 // 131584
#define OFF_QP  SZ_S                           // QH+QL
#define SZ_QP   (2 * 32 * LW * 4)              // 9216
#define OFF_KV  (OFF_QP + SZ_QP)
#define SZ_KV   36864                          // K double buffer (hi+lo x2)
#define ATTN_SMEM_BYTES (OFF_KV + SZ_KV)       // 177664

__global__ __launch_bounds__(256) void attn_kernel(
    const float* __restrict__ Qp, const float* __restrict__ Kp,
    const float* __restrict__ gate, const int* __restrict__ mask,
    float* __restrict__ attn)
{
    extern __shared__ char smraw[];
    float* S = reinterpret_cast<float*>(smraw + OFF_S);
    uint32_t* QH = reinterpret_cast<uint32_t*>(smraw + OFF_QP);
    uint32_t* QL = QH + 32 * LW;
    uint32_t* KVb = reinterpret_cast<uint32_t*>(smraw + OFF_KV);

    const int b = blockIdx.z, h = blockIdx.y;
    const int q0 = blockIdx.x * 32;
    const int tid = threadIdx.x;
    const int wid = tid >> 5, lane = tid & 31;
    const int g = lane >> 2, t = lane & 3;
    const int n = wid * 8;

    // ---- load Q tile [32][64] -> bf16 hi/lo ----
    #pragma unroll
    for (int it = 0; it < 2; it++) {
        int idx = it * 256 + tid;
        int r = idx >> 4, c4 = (idx & 15) * 4;
        float4 v = *reinterpret_cast<const float4*>(
            Qp + (size_t)(b * SEQ + q0 + r) * DM + h * DK + c4);
        uint2 hh, ll; bsplit4(v, hh, ll);
        *reinterpret_cast<uint2*>(&QH[r * LW + (c4 >> 1)]) = hh;
        *reinterpret_cast<uint2*>(&QL[r * LW + (c4 >> 1)]) = ll;
    }

    // ---- prologue: K chunk 0 -> buf 0 ----
    {
        uint32_t* KH = KVb;            uint32_t* KL = KVb + 2304;
        #pragma unroll
        for (int it = 0; it < 4; it++) {
            int idx = it * 256 + tid;
            int r = idx >> 4, c4 = (idx & 15) * 4;
            float4 v = *reinterpret_cast<const float4*>(
                Kp + (size_t)(b * SEQ + r) * DM + h * DK + c4);
            uint2 hh, ll; bsplit4(v, hh, ll);
            *reinterpret_cast<uint2*>(&KH[r * LW + (c4 >> 1)]) = hh;
            *reinterpret_cast<uint2*>(&KL[r * LW + (c4 >> 1)]) = ll;
        }
    }
    __syncthreads();

    const float inv_temp = 0.125f;

    // ---- QK^T: 16 chunks of 64 kv ----
    for (int kc = 0; kc < 16; kc++) {
        int buf = kc & 1;
        uint32_t* KH = KVb + buf * 4608;
        uint32_t* KL = KH + 2304;

        float4 stage[4];
        if (kc < 15) {
            #pragma unroll
            for (int it = 0; it < 4; it++) {
                int idx = it * 256 + tid;
                int r = idx >> 4, c4 = (idx & 15) * 4;
                stage[it] = *reinterpret_cast<const float4*>(
                    Kp + (size_t)(b * SEQ + (kc + 1) * 64 + r) * DM + h * DK + c4);
            }
        }

        float c0[2][4];
        #pragma unroll
        for (int mt = 0; mt < 2; mt++)
            #pragma unroll
            for (int i = 0; i < 4; i++) c0[mt][i] = 0.f;

        #pragma unroll
        for (int ks = 0; ks < 4; ks++) {
            int kk2 = ks * 8;
            uint32_t aH[2][4], aL[2][4], bH[2], bL[2];
            #pragma unroll
            for (int mt = 0; mt < 2; mt++) {
                int base = (mt * 16 + g) * LW + kk2 + t;
                aH[mt][0] = QH[base];     aH[mt][1] = QH[base + 8 * LW];
                aH[mt][2] = QH[base + 4]; aH[mt][3] = QH[base + 8 * LW + 4];
                aL[mt][0] = QL[base];     aL[mt][1] = QL[base + 8 * LW];
                aL[mt][2] = QL[base + 4]; aL[mt][3] = QL[base + 8 * LW + 4];
            }
            int bb = (n + g) * LW + kk2 + t;
            bH[0] = KH[bb]; bH[1] = KH[bb + 4];
            bL[0] = KL[bb]; bL[1] = KL[bb + 4];
            #pragma unroll
            for (int mt = 0; mt < 2; mt++) {
                mma_bf16(c0[mt], aH[mt], bH);
                mma_bf16(c0[mt], aH[mt], bL);
                mma_bf16(c0[mt], aL[mt], bH);
            }
        }

        // epilogue: gate * scale, mask -> S
        #pragma unroll
        for (int mt = 0; mt < 2; mt++) {
            int col = kc * 64 + n + 2 * t;
            #pragma unroll
            for (int half = 0; half < 2; half++) {
                int q = mt * 16 + g + half * 8;
                const float2 gv = *reinterpret_cast<const float2*>(
                    gate + ((size_t)(b * NHEAD + h) * SEQ + q0 + q) * SEQ + col);
                const int2 mv = *reinterpret_cast<const int2*>(
                    mask + ((size_t)(b * SEQ + q0 + q)) * SEQ + col);
                float s0 = mv.x ? -INFINITY : c0[mt][half * 2 + 0] * inv_temp * gv.x;
                float s1 = mv.y ? -INFINITY : c0[mt][half * 2 + 1] * inv_temp * gv.y;
                *reinterpret_cast<float2*>(&S[q * SLD + col]) = make_float2(s0, s1);
            }
        }

        if (kc < 15) {
            uint32_t* NH = KVb + (buf ^ 1) * 4608;
            uint32_t* NL = NH + 2304;
            #pragma unroll
            for (int it = 0; it < 4; it++) {
                int idx = it * 256 + tid;
                int r = idx >> 4, c4 = (idx & 15) * 4;
                uint2 hh, ll; bsplit4(stage[it], hh, ll);
                *reinterpret_cast<uint2*>(&NH[r * LW + (c4 >> 1)]) = hh;
                *reinterpret_cast<uint2*>(&NL[r * LW + (c4 >> 1)]) = ll;
            }
        }
        __syncthreads();
    }

    // ---- softmax: 8 warps x 4 rows; exp kept in regs; write attn ----
    #pragma unroll
    for (int rr = 0; rr < 4; rr++) {
        int r = wid * 4 + rr;
        float* srow = S + r * SLD;
        float4 e[8];
        float mx = -INFINITY;
        #pragma unroll
        for (int i = 0; i < 8; i++) {
            e[i] = *reinterpret_cast<float4*>(&srow[(lane + i * 32) * 4]);
            mx = fmaxf(mx, fmaxf(fmaxf(e[i].x, e[i].y), fmaxf(e[i].z, e[i].w)));
        }
        #pragma unroll
        for (int o = 16; o; o >>= 1) mx = fmaxf(mx, __shfl_xor_sync(0xffffffffu, mx, o));
        float sum = 0.f;
        #pragma unroll
        for (int i = 0; i < 8; i++) {
            e[i].x = __expf(e[i].x - mx); e[i].y = __expf(e[i].y - mx);
            e[i].z = __expf(e[i].z - mx); e[i].w = __expf(e[i].w - mx);
            sum += e[i].x + e[i].y + e[i].z + e[i].w;
        }
        #pragma unroll
        for (int o = 16; o; o >>= 1) sum += __shfl_xor_sync(0xffffffffu, sum, o);
        float inv = 1.f / sum;
        float* arow = attn + ((size_t)(b * NHEAD + h) * SEQ + q0 + r) * SEQ;
        #pragma unroll
        for (int i = 0; i < 8; i++) {
            e[i].x *= inv; e[i].y *= inv; e[i].z *= inv; e[i].w *= inv;
            *reinterpret_cast<float4*>(&arow[(lane + i * 32) * 4]) = e[i];
        }
    }
}

// =====================================================================
// PV GEMM: heads[b,q,h*64+d] = sum_kv P[b,h,q,kv] * V[b,kv,h*64+d]
// Block: 128 q rows x 64 d, K loop over 16 chunks of 64 kv.
// V transposed to [d][kv] in smem via vt_store (proven r5 path).
// =====================================================================
__device__ __forceinline__ void vt_store(uint32_t* VTH, uint32_t* VTL,
                                         float4 v, int kv, int c4, int lane)
{
    float4 p;
    p.x = __shfl_xor_sync(0xffffffffu, v.x, 16);
    p.y = __shfl_xor_sync(0xffffffffu, v.y, 16);
    p.z = __shfl_xor_sync(0xffffffffu, v.z, 16);
    p.w = __shfl_xor_sync(0xffffffffu, v.w, 16);
    int kvp = kv >> 1;
    float e0, o0, e1, o1;
    int d0;
    if ((lane & 16) == 0) { e0 = v.x; o0 = p.x; e1 = v.y; o1 = p.y; d0 = c4; }
    else                  { e0 = p.z; o0 = v.z; e1 = p.w; o1 = v.w; d0 = c4 + 2; }
    uint32_t h, l;
    bsplit2(e0, o0, h, l);
    VTH[d0 * VW + kvp] = h;  VTL[d0 * VW + kvp] = l;
    bsplit2(e1, o1, h, l);
    VTH[(d0 + 1) * VW + kvp] = h;  VTL[(d0 + 1) * VW + kvp] = l;
}

#define PV_SMEM_BYTES ((2 * 128 * LW + 2 * 64 * VW) * 4)   // 54784

__global__ __launch_bounds__(256) void pv_gemm(
    const float* __restrict__ P, const float* __restrict__ Vp,
    float* __restrict__ heads)
{
    extern __shared__ char pvsm[];
    uint32_t* AsH = reinterpret_cast<uint32_t*>(pvsm);
    uint32_t* AsL = AsH + 128 * LW;
    uint32_t* VTH = AsL + 128 * LW;
    uint32_t* VTL = VTH + 64 * VW;

    const int b = blockIdx.z, h = blockIdx.y;
    const int q0 = blockIdx.x * 128;
    const int tid = threadIdx.x;
    const int wid = tid >> 5, lane = tid & 31;
    const int g = lane >> 2, t = lane & 3;
    const int warpM = (wid & 1) * 64;
    const int warpN = (wid >> 1) * 16;

    float c[4][2][4];
    #pragma unroll
    for (int mt = 0; mt < 4; mt++)
        #pragma unroll
        for (int nt = 0; nt < 2; nt++)
            #pragma unroll
            for (int i = 0; i < 4; i++) c[mt][nt][i] = 0.f;

    float4 pa[8], va[4];
    #pragma unroll
    for (int it = 0; it < 8; it++) {
        int idx = it * 256 + tid;
        int r = idx >> 4, c4 = (idx & 15) * 4;
        pa[it] = *reinterpret_cast<const float4*>(
            P + ((size_t)(b * NHEAD + h) * SEQ + q0 + r) * SEQ + c4);
    }
    #pragma unroll
    for (int it = 0; it < 4; it++) {
        int idx = it * 256 + tid;
        int kv = idx >> 4, c4 = (idx & 15) * 4;
        va[it] = *reinterpret_cast<const float4*>(
            Vp + (size_t)(b * SEQ + kv) * DM + h * DK + c4);
    }

    for (int kc = 0; kc < 16; kc++) {
        __syncthreads();
        #pragma unroll
        for (int it = 0; it < 8; it++) {
            int idx = it * 256 + tid;
            int r = idx >> 4, w = (idx & 15) * 2;
            uint2 hh, ll; bsplit4(pa[it], hh, ll);
            *reinterpret_cast<uint2*>(&AsH[r * LW + w]) = hh;
            *reinterpret_cast<uint2*>(&AsL[r * LW + w]) = ll;
        }
        #pragma unroll
        for (int it = 0; it < 4; it++) {
            int idx = it * 256 + tid;
            int kv = idx >> 4, c4 = (idx & 15) * 4;
            vt_store(VTH, VTL, va[it], kv, c4, lane);
        }
        __syncthreads();

        if (kc < 15) {
            #pragma unroll
            for (int it = 0; it < 8; it++) {
                int idx = it * 256 + tid;
                int r = idx >> 4, c4 = (idx & 15) * 4;
                pa[it] = *reinterpret_cast<const float4*>(
                    P + ((size_t)(b * NHEAD + h) * SEQ + q0 + r) * SEQ + (kc + 1) * 64 + c4);
            }
            #pragma unroll
            for (int it = 0; it < 4; it++) {
                int idx = it * 256 + tid;
                int kv = idx >> 4, c4 = (idx & 15) * 4;
                va[it] = *reinterpret_cast<const float4*>(
                    Vp + (size_t)(b * SEQ + (kc + 1) * 64 + kv) * DM + h * DK + c4);
            }
        }

        #pragma unroll
        for (int ks = 0; ks < 4; ks++) {
            int kk2 = ks * 8;
            uint32_t aH[4][4], aL[4][4], bH[2][2], bL[2][2];
            #pragma unroll
            for (int mt = 0; mt < 4; mt++) {
                int base = (warpM + mt * 16 + g) * LW + kk2 + t;
                aH[mt][0] = AsH[base];          aH[mt][1] = AsH[base + 8 * LW];
                aH[mt][2] = AsH[base + 4];      aH[mt][3] = AsH[base + 8 * LW + 4];
                aL[mt][0] = AsL[base];          aL[mt][1] = AsL[base + 8 * LW];
                aL[mt][2] = AsL[base + 4];      aL[mt][3] = AsL[base + 8 * LW + 4];
            }
            #pragma unroll
            for (int nt = 0; nt < 2; nt++) {
                int base = (warpN + nt * 8 + g) * VW + kk2 + t;
                bH[nt][0] = VTH[base]; bH[nt][1] = VTH[base + 4];
                bL[nt][0] = VTL[base]; bL[nt][1] = VTL[base + 4];
            }
            #pragma unroll
            for (int mt = 0; mt < 4; mt++)
                #pragma unroll
                for (int nt = 0; nt < 2; nt++) {
                    mma_bf16(c[mt][nt], aH[mt], bH[nt]);
                    mma_bf16(c[mt][nt], aH[mt], bL[nt]);
                    mma_bf16(c[mt][nt], aL[mt], bH[nt]);
                }
        }
    }

    #pragma unroll
    for (int mt = 0; mt < 4; mt++) {
        int r0 = q0 + warpM + mt * 16 + g;
        int r1 = r0 + 8;
        #pragma unroll
        for (int nt = 0; nt < 2; nt++) {
            int cn = h * DK + warpN + nt * 8 + 2 * t;
            *reinterpret_cast<float2*>(heads + (size_t)(b * SEQ + r0) * DM + cn) =
                make_float2(c[mt][nt][0], c[mt][nt][1]);
            *reinterpret_cast<float2*>(heads + (size_t)(b * SEQ + r1) * DM + cn) =
                make_float2(c[mt][nt][2], c[mt][nt][3]);
        }
    }
}

// ---------------- LayerNorm ----------------
__global__ __launch_bounds__(256) void ln_kernel(
    const float* __restrict__ X, const float* __restrict__ gamma,
    const float* __restrict__ beta, float* __restrict__ out)
{
    __shared__ float sh1[8];
    __shared__ float sh2[8];
    const int row = blockIdx.x;
    const int tid = threadIdx.x;
    const float* x = X + (size_t)row * DM;

    float v[4];
    float s = 0.f;
    #pragma unroll
    for (int i = 0; i < 4; i++) { v[i] = x[tid + i * 256]; s += v[i]; }
    #pragma unroll
    for (int o = 16; o; o >>= 1) s += __shfl_xor_sync(0xffffffffu, s, o);
    if ((tid & 31) == 0) sh1[tid >> 5] = s;
    __syncthreads();
    float tot = 0.f;
    #pragma unroll
    for (int w = 0; w < 8; w++) tot += sh1[w];
    float mu = tot * (1.f / DM);

    float vs = 0.f;
    #pragma unroll
    for (int i = 0; i < 4; i++) { float d = v[i] - mu; vs += d * d; }
    #pragma unroll
    for (int o = 16; o; o >>= 1) vs += __shfl_xor_sync(0xffffffffu, vs, o);
    if ((tid & 31) == 0) sh2[tid >> 5] = vs;
    __syncthreads();
    float tv = 0.f;
    #pragma unroll
    for (int w = 0; w < 8; w++) tv += sh2[w];
    float inv = rsqrtf(tv * (1.f / DM) + LN_EPS);

    float* orow = out + (size_t)row * DM;
    #pragma unroll
    for (int i = 0; i < 4; i++) {
        int c = tid + i * 256;
        orow[c] = (v[i] - mu) * inv * gamma[c] + beta[c];
    }
}

// ---------------- launch ----------------
extern "C" void kernel_launch(void* const* d_in, const int* in_sizes, int n_in,
                              void* d_out, int out_size)
{
    const float* q      = (const float*)d_in[0];
    const float* k      = (const float*)d_in[1];
    const float* v      = (const float*)d_in[2];
    const float* k_gate = (const float*)d_in[3];
    const int*   mask   = (const int*)d_in[4];
    const float* Wq = (const float*)d_in[5];
    const float* bq = (const float*)d_in[6];
    const float* Wk = (const float*)d_in[7];
    const float* bk = (const float*)d_in[8];
    const float* Wv = (const float*)d_in[9];
    const float* bv = (const float*)d_in[10];
    const float* Wo = (const float*)d_in[11];
    const float* bo = (const float*)d_in[12];
    const float* ln_g = (const float*)d_in[13];
    const float* ln_b = (const float*)d_in[14];

    float* out  = (float*)d_out;
    float* attn = out + (size_t)BATCH * SEQ * DM;

    float *Qp, *Kp, *Vp, *heads, *tmp;
    cudaGetSymbolAddress((void**)&Qp, g_Qp);
    cudaGetSymbolAddress((void**)&Kp, g_Kp);
    cudaGetSymbolAddress((void**)&Vp, g_Vp);
    cudaGetSymbolAddress((void**)&heads, g_heads);
    cudaGetSymbolAddress((void**)&tmp, g_tmp);

    cudaFuncSetAttribute(attn_kernel, cudaFuncAttributeMaxDynamicSharedMemorySize,
                         ATTN_SMEM_BYTES);
    cudaFuncSetAttribute(pv_gemm, cudaFuncAttributeMaxDynamicSharedMemorySize,
                         PV_SMEM_BYTES);

    dim3 qkvgrid(DM / 64, MROWS / 128, 3);
    qkv_gemm<<<qkvgrid, 256>>>(q, k, v, Wq, Wk, Wv, bq, bk, bv, Qp, Kp, Vp);

    dim3 agrid(SEQ / 32, NHEAD, BATCH);
    attn_kernel<<<agrid, 256, ATTN_SMEM_BYTES>>>(Qp, Kp, k_gate, mask, attn);

    dim3 pvgrid(SEQ / 128, NHEAD, BATCH);
    pv_gemm<<<pvgrid, 256, PV_SMEM_BYTES>>>(attn, Vp, heads);

    dim3 ogrid(DM / 64, MROWS / 128);
    out_gemm<<<ogrid, 256>>>(heads, Wo, bo, q, tmp);

    ln_kernel<<<MROWS, 256>>>(tmp, ln_g, ln_b, out);
}